// round 1
// baseline (speedup 1.0000x reference)
#include <cuda_runtime.h>
#include <cstdint>
#include <cstddef>

#define T_STEPS 32768
#define CD 512
#define ID 1024
#define NG 2048

// ---------------- scratch (device globals: the sanctioned scratch path) ----
__device__ float g_gx[(size_t)T_STEPS * NG];   // precomputed Wx@x + b, [T][2048]
__device__ float g_hbuf[2 * CD];               // double-buffered h
__device__ unsigned int g_counter;             // monotonic step barrier

// ---------------- init (reset state every graph replay) --------------------
__global__ void init_kernel() {
    int i = blockIdx.x * blockDim.x + threadIdx.x;
    if (i < 2 * CD) g_hbuf[i] = 0.0f;
    if (i == 0) g_counter = 0u;
}

// ---------------- GEMM: g_gx[t][r] = sum_k x[t][k]*W[r][k] + b[r] ----------
#define BM 64
#define BN 64
#define BK 16

__global__ __launch_bounds__(256) void gemm_gx_kernel(
    const float* __restrict__ x,
    const float* __restrict__ wf_w, const float* __restrict__ wf_b,
    const float* __restrict__ wi_w, const float* __restrict__ wi_b,
    const float* __restrict__ wc_w, const float* __restrict__ wc_b,
    const float* __restrict__ wo_w, const float* __restrict__ wo_b)
{
    __shared__ float4 As4[BK][17];   // [k][m/4], padded rows (68 floats)
    __shared__ float4 Bs4[BK][17];
    float* Asf = (float*)As4;
    float* Bsf = (float*)Bs4;

    const int tid = threadIdx.x;
    const int tx = tid & 15;         // output col group (r dim)
    const int ty = tid >> 4;         // output row group (t dim)
    const int r0 = blockIdx.x * BN;
    const int t0 = blockIdx.y * BM;
    const int gate = r0 >> 9;        // BN=64 divides 512, so gate fixed per block
    const int rbase = r0 & 511;

    const float* wsrc = (gate == 0) ? wf_w : (gate == 1) ? wi_w : (gate == 2) ? wc_w : wo_w;
    const float* bsrc = (gate == 0) ? wf_b : (gate == 1) ? wi_b : (gate == 2) ? wc_b : wo_b;

    const int lrow = tid >> 2;   // 0..63
    const int lkc  = tid & 3;    // float4 within the 16-wide k tile

    float acc[4][4];
    #pragma unroll
    for (int i = 0; i < 4; i++)
        #pragma unroll
        for (int j = 0; j < 4; j++) acc[i][j] = 0.0f;

    for (int k0 = 0; k0 < CD; k0 += BK) {
        float4 av = *(const float4*)(x    + (size_t)(t0 + lrow) * CD + k0 + lkc * 4);
        float4 bv = *(const float4*)(wsrc + (size_t)(rbase + lrow) * ID + k0 + lkc * 4);
        __syncthreads();
        #pragma unroll
        for (int q = 0; q < 4; q++) {
            Asf[(lkc * 4 + q) * 68 + lrow] = ((const float*)&av)[q];
            Bsf[(lkc * 4 + q) * 68 + lrow] = ((const float*)&bv)[q];
        }
        __syncthreads();
        #pragma unroll
        for (int k = 0; k < BK; k++) {
            float4 a = As4[k][ty];
            float4 b = Bs4[k][tx];
            float ar[4] = {a.x, a.y, a.z, a.w};
            float br[4] = {b.x, b.y, b.z, b.w};
            #pragma unroll
            for (int i = 0; i < 4; i++)
                #pragma unroll
                for (int j = 0; j < 4; j++) acc[i][j] += ar[i] * br[j];
        }
    }

    float4 bias = *(const float4*)(bsrc + rbase + tx * 4);
    float bb[4] = {bias.x, bias.y, bias.z, bias.w};
    #pragma unroll
    for (int i = 0; i < 4; i++) {
        float4 o;
        o.x = acc[i][0] + bb[0];
        o.y = acc[i][1] + bb[1];
        o.z = acc[i][2] + bb[2];
        o.w = acc[i][3] + bb[3];
        *(float4*)(g_gx + (size_t)(t0 + ty * 4 + i) * NG + r0 + tx * 4) = o;
    }
}

// ---------------- persistent recurrent kernel -------------------------------
#define NB   64        // CTAs (all co-resident on 148 SMs)
#define TPB  256
#define JPB  8         // h indices per CTA (512/64)
#define NROWS 32       // 4 gates * JPB rows per CTA
#define K4   16        // float4 chunks of h per thread (512 / 8 lanes / 4)

__device__ __forceinline__ float sigmoid_f(float x) {
    return __fdividef(1.0f, 1.0f + __expf(-x));
}
__device__ __forceinline__ float tanh_f(float x) {
    float ax = fabsf(x);
    float e  = __expf(-2.0f * ax);
    float t  = __fdividef(1.0f - e, 1.0f + e);
    return copysignf(t, x);
}

__global__ __launch_bounds__(TPB, 1) void lstm_rec_kernel(
    const float* __restrict__ wf_w, const float* __restrict__ wi_w,
    const float* __restrict__ wc_w, const float* __restrict__ wo_w,
    float* __restrict__ d_out)
{
    __shared__ float4 hs4[CD / 4];     // 128 float4 = h broadcast
    __shared__ float gsm[NROWS];

    const int tid  = threadIdx.x;
    const int wrp  = tid >> 5;
    const int lane = tid & 31;
    const int rw   = lane >> 3;        // row-in-warp 0..3
    const int c    = lane & 7;         // lane-in-row 0..7
    const int r    = wrp * 4 + rw;     // local row 0..31
    const int gate = r >> 3;
    const int jj   = r & 7;
    const int j0   = blockIdx.x * JPB;

    // load this thread's 64 h-part weights into registers
    const float* wsrc = (gate == 0) ? wf_w : (gate == 1) ? wi_w : (gate == 2) ? wc_w : wo_w;
    const float4* wp = (const float4*)(wsrc + (size_t)(j0 + jj) * ID + CD);
    float4 wv[K4];
    #pragma unroll
    for (int kk = 0; kk < K4; kk++) wv[kk] = wp[c + 8 * kk];

    const bool owner = (c == 0);
    const float* gxp = g_gx + (size_t)gate * CD + j0 + jj;   // + t*NG per step
    float gx_cur = owner ? gxp[0] : 0.0f;
    float gx_next = 0.0f;

    float c_state = 0.0f;
    float h_last  = 0.0f;

    volatile unsigned int* vcnt = &g_counter;

    for (int t = 0; t < T_STEPS; t++) {
        // prefetch next step's x-part while we wait / compute
        if (owner && (t + 1) < T_STEPS)
            gx_next = __ldg(gxp + (size_t)(t + 1) * NG);

        // grid barrier: wait until all CTAs finished step t-1
        if (tid == 0) {
            unsigned int target = (unsigned int)NB * (unsigned int)t;
            while (*vcnt < target) { }
        }
        __syncthreads();

        // broadcast h(t-1) into smem (L2-coherent .cv loads, bypass stale L1)
        const float4* hb = (const float4*)(g_hbuf + (t & 1) * CD);
        if (tid < CD / 4) hs4[tid] = __ldcv(hb + tid);
        __syncthreads();

        // per-row partial dot: 64 MACs / thread, 4 accumulators
        float a0 = 0.f, a1 = 0.f, a2 = 0.f, a3 = 0.f;
        #pragma unroll
        for (int kk = 0; kk < K4; kk += 4) {
            float4 h0 = hs4[c + 8 * (kk + 0)];
            float4 h1 = hs4[c + 8 * (kk + 1)];
            float4 h2 = hs4[c + 8 * (kk + 2)];
            float4 h3 = hs4[c + 8 * (kk + 3)];
            a0 += wv[kk + 0].x * h0.x + wv[kk + 0].y * h0.y + wv[kk + 0].z * h0.z + wv[kk + 0].w * h0.w;
            a1 += wv[kk + 1].x * h1.x + wv[kk + 1].y * h1.y + wv[kk + 1].z * h1.z + wv[kk + 1].w * h1.w;
            a2 += wv[kk + 2].x * h2.x + wv[kk + 2].y * h2.y + wv[kk + 2].z * h2.z + wv[kk + 2].w * h2.w;
            a3 += wv[kk + 3].x * h3.x + wv[kk + 3].y * h3.y + wv[kk + 3].z * h3.z + wv[kk + 3].w * h3.w;
        }
        float acc = (a0 + a1) + (a2 + a3);
        // reduce the 8 lanes of this row
        acc += __shfl_down_sync(0xffffffffu, acc, 4);
        acc += __shfl_down_sync(0xffffffffu, acc, 2);
        acc += __shfl_down_sync(0xffffffffu, acc, 1);
        if (owner) gsm[r] = acc + gx_cur;
        __syncthreads();

        // gate update + h publish (8 owner threads)
        if (tid < JPB) {
            float gf = gsm[      tid];
            float gi = gsm[ 8 +  tid];
            float gc = gsm[16 +  tid];
            float go = gsm[24 +  tid];
            float f  = sigmoid_f(gf);
            float ii = sigmoid_f(gi);
            float cc = tanh_f(gc);
            float oo = sigmoid_f(go);
            c_state = f * c_state + ii * cc;
            h_last  = tanh_f(c_state) * oo;
            g_hbuf[((t + 1) & 1) * CD + j0 + tid] = h_last;
            __threadfence();                       // release h before counter bump
        }
        __syncthreads();
        if (tid == 0) atomicAdd(&g_counter, 1u);   // arrive (threadfence-reduction pattern)

        gx_cur = gx_next;
    }

    if (tid < JPB) {
        d_out[j0 + tid]      = c_state;   // output = (c, h)
        d_out[CD + j0 + tid] = h_last;
    }
}

// ---------------- launch -----------------------------------------------------
extern "C" void kernel_launch(void* const* d_in, const int* in_sizes, int n_in,
                              void* d_out, int out_size) {
    (void)in_sizes; (void)n_in; (void)out_size;
    const float* x    = (const float*)d_in[0];
    const float* wf_w = (const float*)d_in[1];
    const float* wf_b = (const float*)d_in[2];
    const float* wi_w = (const float*)d_in[3];
    const float* wi_b = (const float*)d_in[4];
    const float* wc_w = (const float*)d_in[5];
    const float* wc_b = (const float*)d_in[6];
    const float* wo_w = (const float*)d_in[7];
    const float* wo_b = (const float*)d_in[8];
    float* out = (float*)d_out;

    init_kernel<<<4, 256>>>();

    dim3 ggrid(NG / BN, T_STEPS / BM);
    gemm_gx_kernel<<<ggrid, 256>>>(x, wf_w, wf_b, wi_w, wi_b, wc_w, wc_b, wo_w, wo_b);

    lstm_rec_kernel<<<NB, TPB>>>(wf_w, wi_w, wc_w, wo_w, out);
}